// round 11
// baseline (speedup 1.0000x reference)
#include <cuda_runtime.h>
#include <cuda_bf16.h>
#include <cuda_fp16.h>
#include <stdint.h>

#define NNODES 50000
#define NPAD   50048            // 391 * 128
#define NEDGES 800000
#define IN_DIM 256
#define HEADS  8
#define NH     512

// ---------------- device scratch ----------------
__device__ __align__(128) __nv_bfloat16 g_Ah[(size_t)NPAD*IN_DIM];
__device__ __align__(128) __nv_bfloat16 g_Al[(size_t)NPAD*IN_DIM];
__device__ __align__(128) __nv_bfloat16 g_Bth[NH*IN_DIM];
__device__ __align__(128) __nv_bfloat16 g_Btl[NH*IN_DIM];
__device__ __align__(128) __half g_Wh16[(size_t)NNODES*NH];   // 51.2 MB (fp16 Wh)
__device__ __align__(16)  float g_s[NNODES*16];
__device__ unsigned g_mkey[16];
__device__ float g_Z[HEADS];
__device__ float g_gate[HEADS];
__device__ int g_cnt[NNODES];          // zeroed by scan1 for next run
__device__ int g_colptr[NNODES+1];
__device__ int g_cur[NNODES];
__device__ int g_bsum[256];
__device__ int g_srow[NEDGES];

// ---------------- helpers ----------------
__device__ __forceinline__ unsigned fkey(float f){
    unsigned b = __float_as_uint(f);
    return (b & 0x80000000u) ? ~b : (b | 0x80000000u);
}
__device__ __forceinline__ float fdec(unsigned k){
    return (k & 0x80000000u) ? __uint_as_float(k ^ 0x80000000u) : __uint_as_float(~k);
}
__device__ __forceinline__ uint32_t s2u(const void* p){
    return (uint32_t)__cvta_generic_to_shared(p);
}
__device__ __forceinline__ void cpa16(uint32_t dst, const void* src){
    asm volatile("cp.async.cg.shared.global [%0], [%1], 16;" :: "r"(dst), "l"(src));
}
__device__ __forceinline__ void ldsm4(uint32_t* r, uint32_t addr){
    asm volatile("ldmatrix.sync.aligned.m8n8.x4.shared.b16 {%0,%1,%2,%3}, [%4];"
        : "=r"(r[0]), "=r"(r[1]), "=r"(r[2]), "=r"(r[3]) : "r"(addr));
}
__device__ __forceinline__ void mma_bf16(float* d, const uint32_t* a, uint32_t b0, uint32_t b1){
    asm volatile("mma.sync.aligned.m16n8k16.row.col.f32.bf16.bf16.f32 "
        "{%0,%1,%2,%3},{%4,%5,%6,%7},{%8,%9},{%0,%1,%2,%3};"
        : "+f"(d[0]), "+f"(d[1]), "+f"(d[2]), "+f"(d[3])
        : "r"(a[0]), "r"(a[1]), "r"(a[2]), "r"(a[3]), "r"(b0), "r"(b1));
}

// ---------------- fused setup ----------------
__global__ void k_setup(const float* __restrict__ x, const int* __restrict__ ei,
                        const float* __restrict__ W, const float* __restrict__ gate,
                        float* __restrict__ out){
    int tid = blockIdx.x*blockDim.x + threadIdx.x;
    if (tid < 8)  g_Z[tid] = 0.f;
    if (tid < 16) g_mkey[tid] = 0u;
    if (tid == 0){
        float m = -1e30f;
        for (int h = 0; h < HEADS; h++) m = fmaxf(m, gate[h]);
        float ex[HEADS]; float z = 0.f;
        for (int h = 0; h < HEADS; h++){ ex[h] = __expf(gate[h]-m); z += ex[h]; }
        for (int h = 0; h < HEADS; h++) g_gate[h] = ex[h]/z;
    }
    if (tid < NNODES*16)
        reinterpret_cast<float4*>(out)[tid] = make_float4(0.f,0.f,0.f,0.f);
    if (tid < NEDGES) atomicAdd(&g_cnt[ei[NEDGES + tid]], 1);
    if (tid < NH*IN_DIM){
        int n = tid >> 8, d = tid & 255;
        int h = n >> 6, o = n & 63;
        float v = W[(size_t)h*IN_DIM*64 + d*64 + o];
        __nv_bfloat16 hb = __float2bfloat16(v);
        __nv_bfloat16 lb = __float2bfloat16(v - __bfloat162float(hb));
        g_Bth[tid] = hb;
        g_Btl[tid] = lb;
    }
    if (tid < NPAD*IN_DIM/4){
        int base = tid*4;
        int row = base / IN_DIM;
        float4 v = make_float4(0.f,0.f,0.f,0.f);
        if (row < NNODES) v = *reinterpret_cast<const float4*>(x + base);
        float vv[4] = {v.x, v.y, v.z, v.w};
        unsigned short hb[4], lb[4];
#pragma unroll
        for (int j = 0; j < 4; j++){
            __nv_bfloat16 h = __float2bfloat16(vv[j]);
            __nv_bfloat16 l = __float2bfloat16(vv[j] - __bfloat162float(h));
            hb[j] = __bfloat16_as_ushort(h);
            lb[j] = __bfloat16_as_ushort(l);
        }
        uint2 ph = make_uint2((unsigned)hb[0] | ((unsigned)hb[1]<<16),
                              (unsigned)hb[2] | ((unsigned)hb[3]<<16));
        uint2 pl = make_uint2((unsigned)lb[0] | ((unsigned)lb[1]<<16),
                              (unsigned)lb[2] | ((unsigned)lb[3]<<16));
        *reinterpret_cast<uint2*>(reinterpret_cast<char*>(g_Ah) + (size_t)base*2) = ph;
        *reinterpret_cast<uint2*>(reinterpret_cast<char*>(g_Al) + (size_t)base*2) = pl;
    }
}

// ---------------- CSC scans ----------------
__global__ void k_scan1(){
    __shared__ int sd[256];
    int tid = threadIdx.x;
    int i = blockIdx.x*256 + tid;
    int v = (i < NNODES) ? g_cnt[i] : 0;
    if (i < NNODES) g_cnt[i] = 0;
    sd[tid] = v; __syncthreads();
    for (int off = 1; off < 256; off <<= 1){
        int t = (tid >= off) ? sd[tid - off] : 0;
        __syncthreads();
        sd[tid] += t;
        __syncthreads();
    }
    if (i < NNODES) g_colptr[i] = sd[tid] - v;
    if (tid == 255) g_bsum[blockIdx.x] = sd[255];
}
__global__ void k_scan23(){
    __shared__ int sd[256];
    __shared__ int s_off;
    int tid = threadIdx.x;
    const int nb = (NNODES + 255)/256;
    int v = (tid < nb) ? g_bsum[tid] : 0;
    sd[tid] = v; __syncthreads();
    for (int off = 1; off < 256; off <<= 1){
        int t = (tid >= off) ? sd[tid - off] : 0;
        __syncthreads();
        sd[tid] += t;
        __syncthreads();
    }
    if (tid == (int)blockIdx.x) s_off = sd[tid] - v;
    __syncthreads();
    int i = blockIdx.x*256 + tid;
    if (i < NNODES){
        int p = g_colptr[i] + s_off;
        g_colptr[i] = p;
        g_cur[i]    = p;
    }
    if (blockIdx.x == 0 && tid == 0) g_colptr[NNODES] = NEDGES;
}

// ---------------- big kernel: fused 3-product stage loop (Ah,Al,Bh,Bl per K-eighth) ----------------
// stage = 4 tiles (Ah, Al, Bh, Bl), each 128 rows x 32 cols bf16 (64B rows) = 8192 B
#define TILE     8192
#define ST       32768                  // stage size
#define OFF_A    0                      // 3 stages
#define OFF_BIAS 98304                  // 512 f
#define OFF_SA   100352                 // 1024 f
#define OFF_SSM  104448                 // 128*16 f
#define OFF_SMK  112640                 // 16 u32
#define SMEM_BIG 112704

// load one 128x32 bf16 tile (64B rows, swizzle qq ^ ((r>>1)&3))
__device__ __forceinline__ void load_tile32(uint32_t dstbase, const __nv_bfloat16* __restrict__ src,
                                            int tid){
#pragma unroll
    for (int i = 0; i < 2; i++){
        int idx = tid + i*256;
        int r = idx >> 2, qq = idx & 3;
        uint32_t off = (uint32_t)(r*64 + ((qq ^ ((r >> 1) & 3)) << 4));
        cpa16(dstbase + off, src + (size_t)r*IN_DIM + qq*8);
    }
}

// compute all 3 split products from one stage: d += Ah*Bh + Ah*Bl + Al*Bh
__device__ __forceinline__ void gemm_stage(uint32_t sb_st, int wm, int wn, int lane,
                                           float d[4][4][4]){
    int lr = lane & 15;
    int qh = lane >> 4;
    uint32_t arow[4], brow[2];
    int asw[4], bsw[2];
#pragma unroll
    for (int mi = 0; mi < 4; mi++){
        int row = wm + mi*16 + lr;
        arow[mi] = sb_st + row*64;
        asw[mi]  = (row >> 1) & 3;
    }
#pragma unroll
    for (int bi = 0; bi < 2; bi++){
        int row = wn + bi*16 + lr;
        brow[bi] = sb_st + 2*TILE + row*64;    // Bh tile
        bsw[bi]  = (row >> 1) & 3;
    }
#pragma unroll
    for (int ks = 0; ks < 2; ks++){
        int q = ks*2 + qh;
        uint32_t af[4][4], bfh[2][4], bfl[2][4];
#pragma unroll
        for (int mi = 0; mi < 4; mi++)
            ldsm4(af[mi], arow[mi] + ((q ^ asw[mi]) << 4));          // Ah
#pragma unroll
        for (int bi = 0; bi < 2; bi++){
            uint32_t boff = ((q ^ bsw[bi]) << 4);
            ldsm4(bfh[bi], brow[bi] + boff);                         // Bh
            ldsm4(bfl[bi], brow[bi] + TILE + boff);                  // Bl
        }
        // Ah*Bh + Ah*Bl
#pragma unroll
        for (int mi = 0; mi < 4; mi++)
#pragma unroll
            for (int ni = 0; ni < 4; ni++){
                int bi = ni >> 1, sub = ni & 1;
                mma_bf16(d[mi][ni], af[mi], bfh[bi][sub], bfh[bi][sub + 2]);
                mma_bf16(d[mi][ni], af[mi], bfl[bi][sub], bfl[bi][sub + 2]);
            }
        // Al*Bh (reuse af regs)
#pragma unroll
        for (int mi = 0; mi < 4; mi++)
            ldsm4(af[mi], arow[mi] + TILE + ((q ^ asw[mi]) << 4));   // Al
#pragma unroll
        for (int mi = 0; mi < 4; mi++)
#pragma unroll
            for (int ni = 0; ni < 4; ni++){
                int bi = ni >> 1, sub = ni & 1;
                mma_bf16(d[mi][ni], af[mi], bfh[bi][sub], bfh[bi][sub + 2]);
            }
    }
}

// grid = (4, 391)
__global__ __launch_bounds__(256,2) void k_big(const float* __restrict__ bias,
                                               const float* __restrict__ a_vec,
                                               const int* __restrict__ ei){
    extern __shared__ char smem[];
    uint32_t sb = s2u(smem);
    float*    s_bias = (float*)(smem + OFF_BIAS);
    float*    s_a    = (float*)(smem + OFF_SA);
    float*    s_sm   = (float*)(smem + OFF_SSM);
    unsigned* s_mk   = (unsigned*)(smem + OFF_SMK);

    int tid = threadIdx.x, wid = tid >> 5, lane = tid & 31;
    int wm = (wid >> 2)*64, wn = (wid & 3)*32;
    int m0 = blockIdx.y*128, n0 = blockIdx.x*128;

    for (int i = tid; i < 512;  i += 256) s_bias[i] = bias[i];
    for (int i = tid; i < 1024; i += 256) s_a[i]    = a_vec[i];
    for (int i = tid; i < 2048; i += 256) s_sm[i]   = 0.f;
    if (tid < 16) s_mk[tid] = 0u;

    float d[4][4][4];
#pragma unroll
    for (int mi = 0; mi < 4; mi++)
#pragma unroll
        for (int ni = 0; ni < 4; ni++)
#pragma unroll
            for (int k = 0; k < 4; k++) d[mi][ni][k] = 0.f;

    const __nv_bfloat16* Abase  = g_Ah  + (size_t)m0*IN_DIM;
    const __nv_bfloat16* Albase = g_Al  + (size_t)m0*IN_DIM;
    const __nv_bfloat16* Bbase  = g_Bth + (size_t)n0*IN_DIM;
    const __nv_bfloat16* Blbase = g_Btl + (size_t)n0*IN_DIM;

    // 8 K-eighth stages (32 cols each); each stage holds Ah,Al,Bh,Bl
    // prologue: stages for chunks 0,1
#pragma unroll
    for (int c = 0; c < 2; c++){
        uint32_t st = sb + OFF_A + c*ST;
        load_tile32(st,          Abase  + c*32, tid);
        load_tile32(st +   TILE, Albase + c*32, tid);
        load_tile32(st + 2*TILE, Bbase  + c*32, tid);
        load_tile32(st + 3*TILE, Blbase + c*32, tid);
        asm volatile("cp.async.commit_group;" ::: "memory");
    }

    // CSC reorder: 512 edges per CTA, hidden behind prologue loads
    {
        int cta = blockIdx.y*4 + blockIdx.x;
#pragma unroll
        for (int r = 0; r < 2; r++){
            int e = cta*512 + r*256 + tid;
            if (e < NEDGES){
                int row = ei[e], col = ei[NEDGES + e];
                int pos = atomicAdd(&g_cur[col], 1);
                g_srow[pos] = row;
            }
        }
    }

    for (int c = 0; c < 8; c++){
        asm volatile("cp.async.wait_group 1;" ::: "memory");
        __syncthreads();
        int cn = c + 2;
        if (cn < 8){
            uint32_t st = sb + OFF_A + (cn % 3)*ST;
            load_tile32(st,          Abase  + cn*32, tid);
            load_tile32(st +   TILE, Albase + cn*32, tid);
            load_tile32(st + 2*TILE, Bbase  + cn*32, tid);
            load_tile32(st + 3*TILE, Blbase + cn*32, tid);
        }
        asm volatile("cp.async.commit_group;" ::: "memory");   // possibly empty group
        gemm_stage(sb + OFF_A + (c % 3)*ST, wm, wn, lane, d);
    }

    // -------- epilogue: bias, fp16 Wh store, fused s-dots + node max --------
    int h = (n0 + wn) >> 6;
    const float* aS = s_a + h*128;
    const float* aD = s_a + h*128 + 64;
    float accS[4][2], accD[4][2];
#pragma unroll
    for (int mi = 0; mi < 4; mi++){ accS[mi][0]=accS[mi][1]=accD[mi][0]=accD[mi][1]=0.f; }

#pragma unroll
    for (int mi = 0; mi < 4; mi++){
#pragma unroll
        for (int ni = 0; ni < 4; ni++){
            int C = wn + ni*8 + (lane & 3)*2;
            int o = C & 63;
            float b0 = s_bias[n0 + C], b1 = s_bias[n0 + C + 1];
#pragma unroll
            for (int rr = 0; rr < 2; rr++){
                float v0 = d[mi][ni][rr*2 + 0] + b0;
                float v1 = d[mi][ni][rr*2 + 1] + b1;
                int R = wm + mi*16 + (lane >> 2) + rr*8;
                int gm = m0 + R;
                if (gm < NNODES){
                    __half2 hv = __floats2half2_rn(v0, v1);
                    *reinterpret_cast<__half2*>(g_Wh16 + (size_t)gm*NH + n0 + C) = hv;
                }
                accS[mi][rr] += v0*aS[o] + v1*aS[o+1];
                accD[mi][rr] += v0*aD[o] + v1*aD[o+1];
            }
        }
    }
#pragma unroll
    for (int mi = 0; mi < 4; mi++)
#pragma unroll
        for (int rr = 0; rr < 2; rr++){
            float vs = accS[mi][rr], vd = accD[mi][rr];
            vs += __shfl_xor_sync(0xffffffffu, vs, 1);
            vs += __shfl_xor_sync(0xffffffffu, vs, 2);
            vd += __shfl_xor_sync(0xffffffffu, vd, 1);
            vd += __shfl_xor_sync(0xffffffffu, vd, 2);
            if ((lane & 3) == 0){
                int R = wm + mi*16 + (lane >> 2) + rr*8;
                atomicAdd(&s_sm[R*16 + h],     vs);
                atomicAdd(&s_sm[R*16 + 8 + h], vd);
            }
        }
    __syncthreads();
    int h0 = n0 >> 6;
    for (int i = tid; i < 512; i += 256){
        int r = i >> 2, jj = i & 3;
        int j = h0 + (jj & 1) + (jj >> 1)*8;
        int gm = m0 + r;
        if (gm < NNODES){
            float v = s_sm[r*16 + j];
            g_s[gm*16 + j] = v;
            atomicMax(&s_mk[j], fkey(v));
        }
    }
    __syncthreads();
    if (tid < 4){
        int j = h0 + (tid & 1) + (tid >> 1)*8;
        unsigned k = s_mk[j];
        if (k) atomicMax(&g_mkey[j], k);
    }
}

// ---------------- per-head Z ----------------
__global__ void k_Z(const int* __restrict__ ei){
    __shared__ float sM[8];
    __shared__ float ssum[8];
    if (threadIdx.x < 8){
        float m = fdec(g_mkey[threadIdx.x]) + fdec(g_mkey[8 + threadIdx.x]);
        sM[threadIdx.x] = (m > 0.f) ? m : 0.01f*m;
        ssum[threadIdx.x] = 0.f;
    }
    __syncthreads();
    int p = blockIdx.x*blockDim.x + threadIdx.x;
    int row = ei[p], col = ei[NEDGES + p];
    float4 s0 = *reinterpret_cast<const float4*>(g_s + row*16);
    float4 s1 = *reinterpret_cast<const float4*>(g_s + row*16 + 4);
    float4 d0 = *reinterpret_cast<const float4*>(g_s + col*16 + 8);
    float4 d1 = *reinterpret_cast<const float4*>(g_s + col*16 + 12);
    float sv[8] = {s0.x,s0.y,s0.z,s0.w,s1.x,s1.y,s1.z,s1.w};
    float dv[8] = {d0.x,d0.y,d0.z,d0.w,d1.x,d1.y,d1.z,d1.w};
    float ex[8];
#pragma unroll
    for (int h = 0; h < 8; h++){
        float t = sv[h] + dv[h];
        t = (t > 0.f) ? t : 0.01f*t;
        ex[h] = __expf(t - sM[h]);
    }
#pragma unroll
    for (int h = 0; h < 8; h++)
#pragma unroll
        for (int off = 16; off; off >>= 1)
            ex[h] += __shfl_xor_sync(0xffffffffu, ex[h], off);
    if ((threadIdx.x & 31) == 0){
#pragma unroll
        for (int h = 0; h < 8; h++) atomicAdd(&ssum[h], ex[h]);
    }
    __syncthreads();
    if (threadIdx.x < 8) atomicAdd(&g_Z[threadIdx.x], ssum[threadIdx.x]);
}

// ---------------- CSC scatter: warp per col, inline w, 2-edge unroll ----------------
__global__ __launch_bounds__(256) void k_scatter(float* __restrict__ out){
    __shared__ float sc[8];
    __shared__ float sMs[8];
    if (threadIdx.x < 8){
        sc[threadIdx.x] = g_gate[threadIdx.x] / g_Z[threadIdx.x];
        float m = fdec(g_mkey[threadIdx.x]) + fdec(g_mkey[8 + threadIdx.x]);
        sMs[threadIdx.x] = (m > 0.f) ? m : 0.01f*m;
    }
    __syncthreads();
    int warp = threadIdx.x >> 5, lane = threadIdx.x & 31;
    int c = blockIdx.x*8 + warp;
    if (c >= NNODES) return;
    int p0 = g_colptr[c], p1 = g_colptr[c+1];
    if (p0 == p1) return;
    const __half* wp = g_Wh16 + (size_t)c*NH;
    float whv[16];
#pragma unroll
    for (int h = 0; h < 8; h++){
        whv[h]     = __half2float(wp[h*64 + lane]);
        whv[8 + h] = __half2float(wp[h*64 + 32 + lane]);
    }
    int hh = lane & 7;
    float sd = g_s[c*16 + 8 + hh];
    float ch = sc[hh];
    float Mh = sMs[hh];

    int p = p0;
    for (; p + 2 <= p1; p += 2){
        float wv = 0.f;
        int rowv = 0;
        if (lane < 16){
            rowv = g_srow[p + (lane >> 3)];
            float t = g_s[rowv*16 + hh] + sd;
            t = (t > 0.f) ? t : 0.01f*t;
            wv = ch * __expf(t - Mh);
        }
        float a00 = 0.f, a01 = 0.f, a10 = 0.f, a11 = 0.f;
#pragma unroll
        for (int h = 0; h < 8; h++){
            float w0 = __shfl_sync(0xffffffffu, wv, h);
            float w1 = __shfl_sync(0xffffffffu, wv, 8 + h);
            a00 += w0 * whv[h];
            a01 += w0 * whv[8 + h];
            a10 += w1 * whv[h];
            a11 += w1 * whv[8 + h];
        }
        int r0 = __shfl_sync(0xffffffffu, rowv, 0);
        int r1 = __shfl_sync(0xffffffffu, rowv, 8);
        atomicAdd(out + (size_t)r0*64 + lane,      a00);
        atomicAdd(out + (size_t)r0*64 + 32 + lane, a01);
        atomicAdd(out + (size_t)r1*64 + lane,      a10);
        atomicAdd(out + (size_t)r1*64 + 32 + lane, a11);
    }
    if (p < p1){
        float wv = 0.f;
        int rowv = 0;
        if (lane < 8){
            rowv = g_srow[p];
            float t = g_s[rowv*16 + hh] + sd;
            t = (t > 0.f) ? t : 0.01f*t;
            wv = ch * __expf(t - Mh);
        }
        float a0 = 0.f, a1 = 0.f;
#pragma unroll
        for (int h = 0; h < 8; h++){
            float w = __shfl_sync(0xffffffffu, wv, h);
            a0 += w * whv[h];
            a1 += w * whv[8 + h];
        }
        int r0 = __shfl_sync(0xffffffffu, rowv, 0);
        atomicAdd(out + (size_t)r0*64 + lane,      a0);
        atomicAdd(out + (size_t)r0*64 + 32 + lane, a1);
    }
}

// ---------------- launch ----------------
extern "C" void kernel_launch(void* const* d_in, const int* in_sizes, int n_in,
                              void* d_out, int out_size){
    const float* x    = (const float*)d_in[0];
    const int*   ei   = (const int*)  d_in[1];
    const float* W    = (const float*)d_in[2];
    const float* b    = (const float*)d_in[3];
    const float* a    = (const float*)d_in[4];
    const float* gate = (const float*)d_in[5];
    float* out = (float*)d_out;

    cudaFuncSetAttribute(k_big, cudaFuncAttributeMaxDynamicSharedMemorySize, SMEM_BIG);

    k_setup<<<(NPAD*IN_DIM/4 + 255)/256, 256>>>(x, ei, W, gate, out);
    k_scan1<<<(NNODES + 255)/256, 256>>>();
    k_scan23<<<(NNODES + 255)/256, 256>>>();
    dim3 gg(4, NPAD/128);
    k_big<<<gg, 256, SMEM_BIG>>>(b, a, ei);    // ncu captured slot
    k_Z<<<NEDGES/256, 256>>>(ei);
    k_scatter<<<(NNODES + 7)/8, 256>>>(out);
}